// round 9
// baseline (speedup 1.0000x reference)
#include <cuda_runtime.h>
#include <cstdint>
#include <cstddef>

#define NNET 16
#define BB   16
#define TT   512
#define II   256
#define HH   512
#define GROUPS 8          // CTAs per network in the scan kernel
#define OSL  64           // output channels per scan CTA
#define OUT_XP ((size_t)NNET * BB * TT * HH)   // offset of h_n section in d_out

// Persistent state for the scan (double-buffered h + per-net arrival counters).
// __device__ globals: no allocation APIs anywhere (harness rule).
__device__ float    g_hbuf[2][NNET][BB][HH];
__device__ unsigned g_cnt[NNET];

// ---------------------------------------------------------------------------
// f32x2 helpers (FFMA2 is PTX-only; ptxas never auto-generates it)
// ---------------------------------------------------------------------------
__device__ __forceinline__ void fma2(uint64_t& acc, uint64_t a, uint64_t b) {
    asm("fma.rn.f32x2 %0, %1, %2, %0;" : "+l"(acc) : "l"(a), "l"(b));
}
__device__ __forceinline__ float hsum2(uint64_t v) {
    float lo, hi;
    asm("mov.b64 {%0, %1}, %2;" : "=f"(lo), "=f"(hi) : "l"(v));
    return lo + hi;
}
__device__ __forceinline__ void lds_v2u64(uint64_t& a, uint64_t& b, unsigned saddr) {
    asm("ld.shared.v2.b64 {%0, %1}, [%2];" : "=l"(a), "=l"(b) : "r"(saddr));
}
__device__ __forceinline__ void ldg_nc_v2u64(uint64_t& a, uint64_t& b, const float* p) {
    asm("ld.global.nc.v2.b64 {%0, %1}, [%2];" : "=l"(a), "=l"(b) : "l"(p));
}

// ---------------------------------------------------------------------------
// Phase 1: x_proj[n,m,h] = sum_i x[n,m,i] * w_ih[n,h,i] + b_ih[n,h]
//   m = b*T + t (x is contiguous that way). Written straight into d_out's
//   output region; phase 2 overwrites in place with tanh(...).
// Tiling: BM=128, BN=64, BK=16; 256 threads; per-thread micro-tile 8m x 4n,
// n's strided by 16 to dodge smem bank conflicts on the W vector loads.
// ---------------------------------------------------------------------------
__global__ __launch_bounds__(256, 2) void xproj_kernel(
    const float* __restrict__ x, const float* __restrict__ w_ih,
    const float* __restrict__ b_ih, float* __restrict__ out)
{
    __shared__ float As[128][20];   // padded rows (80B) for conflict avoidance
    __shared__ float Ws[64][20];

    const int tid = threadIdx.x;
    const int net = blockIdx.z;
    const int bm  = blockIdx.x * 128;
    const int bn  = blockIdx.y * 64;
    const int tx  = tid & 15;       // n-dim: locals {tx, tx+16, tx+32, tx+48}
    const int ty  = tid >> 4;       // m-dim: locals ty*8 .. ty*8+7

    const float* xA = x    + (size_t)net * BB * TT * II + (size_t)bm * II;
    const float* xW = w_ih + (size_t)net * HH * II      + (size_t)bn * II;

    uint64_t acc[8][4];
#pragma unroll
    for (int i = 0; i < 8; i++)
#pragma unroll
        for (int j = 0; j < 4; j++) acc[i][j] = 0ull;

    const int arow = tid >> 2, ac4 = tid & 3;   // 128 rows x 4 float4 -> 2 per thread
    const int wrow = tid >> 2, wc4 = tid & 3;   // 64 rows x 4 float4  -> 1 per thread

    for (int kt = 0; kt < II; kt += 16) {
        float4 a0 = *(const float4*)(xA + (size_t)arow        * II + kt + ac4 * 4);
        float4 a1 = *(const float4*)(xA + (size_t)(arow + 64) * II + kt + ac4 * 4);
        float4 w0 = *(const float4*)(xW + (size_t)wrow        * II + kt + wc4 * 4);
        __syncthreads();                      // prior compute done before overwrite
        *(float4*)&As[arow][ac4 * 4]      = a0;
        *(float4*)&As[arow + 64][ac4 * 4] = a1;
        *(float4*)&Ws[wrow][wc4 * 4]      = w0;
        __syncthreads();
#pragma unroll
        for (int kk = 0; kk < 16; kk += 4) {
            uint64_t wv[4][2];
#pragma unroll
            for (int ni = 0; ni < 4; ni++) {
                unsigned sa = (unsigned)__cvta_generic_to_shared(&Ws[tx + ni * 16][kk]);
                lds_v2u64(wv[ni][0], wv[ni][1], sa);
            }
#pragma unroll
            for (int mi = 0; mi < 8; mi++) {
                uint64_t a01, a23;
                unsigned sa = (unsigned)__cvta_generic_to_shared(&As[ty * 8 + mi][kk]);
                lds_v2u64(a01, a23, sa);
#pragma unroll
                for (int ni = 0; ni < 4; ni++) {
                    fma2(acc[mi][ni], a01, wv[ni][0]);
                    fma2(acc[mi][ni], a23, wv[ni][1]);
                }
            }
        }
    }

    float bias[4];
#pragma unroll
    for (int ni = 0; ni < 4; ni++) bias[ni] = b_ih[net * HH + bn + tx + ni * 16];

    float* orow = out + (size_t)net * BB * TT * HH + (size_t)(bm + ty * 8) * HH + bn;
#pragma unroll
    for (int mi = 0; mi < 8; mi++)
#pragma unroll
        for (int ni = 0; ni < 4; ni++)
            orow[(size_t)mi * HH + tx + ni * 16] = hsum2(acc[mi][ni]) + bias[ni];
}

// ---------------------------------------------------------------------------
// Phase 2: persistent recurrent scan.
// 128 CTAs = 16 nets x 8 groups. CTA owns 64 channels x 16 batches.
// 8 warps = 2 o-groups x 4-way K-split; lane = 1 channel, 16 f32x2 accums.
// h_prev staged in smem (L2 loads), w_hh streamed via LDG.nc (L1-resident).
// Per-step cross-CTA barrier via monotonic global counter + double buffer.
// ---------------------------------------------------------------------------
__global__ __launch_bounds__(256, 1) void rnn_scan_kernel(
    const float* __restrict__ w_hh, const float* __restrict__ b_hh,
    float* __restrict__ out)
{
    __shared__ float h_s[BB][HH];          // 32 KB; first 16 KB reused for reduction
    float* red = &h_s[0][0];

    const int tid   = threadIdx.x;
    const int n     = blockIdx.x >> 3;
    const int grp   = blockIdx.x & 7;
    const int wid   = tid >> 5, lane = tid & 31;
    const int ogrp  = wid & 1,  ksp  = wid >> 1;
    const int o_loc = ogrp * 32 + lane;
    const int o_glb = grp * OSL + o_loc;
    const int kbase = ksp * 128;

    const float* wrow = w_hh + ((size_t)n * HH + o_glb) * HH + kbase;
    float* hb = &g_hbuf[0][0][0][0];

    // Per-thread epilogue constants: thread handles flat outputs j = r*256+tid,
    // j = b*64 + oo.
    float  bh[4];
    size_t xoff[4];   // index into out[] minus t*HH
    int    hoff[4];   // index into one h buffer slab
#pragma unroll
    for (int r = 0; r < 4; r++) {
        int j = (r << 8) + tid;
        int b = j >> 6, oo = j & 63;
        int og = grp * OSL + oo;
        bh[r]   = b_hh[n * HH + og];
        xoff[r] = ((size_t)(n * BB + b)) * TT * HH + og;
        hoff[r] = (n * BB + b) * HH + og;
    }
    const int SLAB = NNET * BB * HH;

    unsigned target = 0;

    for (int t = 0; t < TT; ++t) {
        const int p = t & 1;

        // Prefetch this step's x_proj values (hide L2 latency behind the GEMM).
        float xv[4];
#pragma unroll
        for (int r = 0; r < 4; r++) xv[r] = out[xoff[r] + (size_t)t * HH];

        // Stage h_prev into smem. __ldcg: bypass L1 (written by other CTAs).
        const float4* src = (const float4*)(hb + (size_t)p * SLAB + n * BB * HH);
        float4* dst = (float4*)&h_s[0][0];
#pragma unroll
        for (int i = 0; i < 8; i++) dst[tid + (i << 8)] = __ldcg(src + tid + (i << 8));
        __syncthreads();

        // GEMM: acc2[b] += h[b][k..] * w[o][k..], k paired in f32x2.
        uint64_t acc[16];
#pragma unroll
        for (int b = 0; b < 16; b++) acc[b] = 0ull;
        const unsigned hbase = (unsigned)__cvta_generic_to_shared(&h_s[0][kbase]);
        const float* wp = wrow;
#pragma unroll 2
        for (int kk = 0; kk < 128; kk += 4) {
            uint64_t w01, w23;
            ldg_nc_v2u64(w01, w23, wp + kk);
#pragma unroll
            for (int b = 0; b < 16; b++) {
                uint64_t h01, h23;
                lds_v2u64(h01, h23, hbase + b * (HH * 4) + kk * 4);
                fma2(acc[b], h01, w01);
                fma2(acc[b], h23, w23);
            }
        }
        __syncthreads();   // all warps done reading h_s -> safe to reuse as red

        // K-split partials: red[(b*64 + o_loc)*4 + ksp]
#pragma unroll
        for (int b = 0; b < 16; b++)
            red[((((b << 6) | o_loc)) << 2) + ksp] = hsum2(acc[b]);
        __syncthreads();

        // Reduce 4 partials, add bias + x_proj, tanh, store everywhere needed.
        const int pnew = p ^ 1;
#pragma unroll
        for (int r = 0; r < 4; r++) {
            int j = (r << 8) + tid;
            float4 pr = *(const float4*)&red[j << 2];
            float s  = (pr.x + pr.y) + (pr.z + pr.w) + bh[r];
            float hv = tanhf(xv[r] + s);
            out[xoff[r] + (size_t)t * HH] = hv;
            hb[(size_t)pnew * SLAB + hoff[r]] = hv;
            if (t == TT - 1) out[OUT_XP + hoff[r]] = hv;
        }

        // Cross-CTA step barrier for this network (8 CTAs).
        __threadfence();
        __syncthreads();
        target += GROUPS;
        if (tid == 0) {
            atomicAdd(&g_cnt[n], 1u);
            volatile unsigned* vc = (volatile unsigned*)&g_cnt[n];
            while (*vc < target) { }
        }
        __syncthreads();
    }
}

// ---------------------------------------------------------------------------
// Launch. Inputs (metadata order): x, w_ih, w_hh, b_ih, b_hh. Output: fp32
// concat(output[N,B,T,H], h_n[N,B,H]).
// ---------------------------------------------------------------------------
extern "C" void kernel_launch(void* const* d_in, const int* in_sizes, int n_in,
                              void* d_out, int out_size)
{
    (void)in_sizes; (void)n_in; (void)out_size;
    const float* x    = (const float*)d_in[0];
    const float* w_ih = (const float*)d_in[1];
    const float* w_hh = (const float*)d_in[2];
    const float* b_ih = (const float*)d_in[3];
    const float* b_hh = (const float*)d_in[4];
    float* out = (float*)d_out;

    // Zero h0 buffer (slab 0) and the arrival counters — graph-capturable,
    // re-executed on every replay so the kernel stays deterministic.
    void* hb = nullptr;  void* cp = nullptr;
    cudaGetSymbolAddress(&hb, g_hbuf);
    cudaGetSymbolAddress(&cp, g_cnt);
    cudaMemsetAsync(hb, 0, sizeof(float) * NNET * BB * HH, 0);
    cudaMemsetAsync(cp, 0, sizeof(unsigned) * NNET, 0);

    dim3 g1(TT * BB / 128, HH / 64, NNET);   // 64 x 8 x 16
    xproj_kernel<<<g1, 256>>>(x, w_ih, b_ih, out);

    rnn_scan_kernel<<<NNET * GROUPS, 256>>>(w_hh, b_hh, out);
}

// round 10
// speedup vs baseline: 1.4334x; 1.4334x over previous
#include <cuda_runtime.h>
#include <cstdint>
#include <cstddef>

#define NNET 16
#define BB   16
#define TT   512
#define II   256
#define HH   512
#define GROUPS 8          // CTAs per network in the scan kernel
#define OSL  64           // output channels per scan CTA
#define OUT_XP ((size_t)NNET * BB * TT * HH)   // offset of h_n section in d_out

// Persistent state for the scan (double-buffered h + per-net arrival counters).
__device__ float    g_hbuf[2][NNET][BB][HH];
__device__ unsigned g_cnt[NNET];

// ---------------------------------------------------------------------------
// f32x2 helpers (FFMA2 is PTX-only; ptxas never auto-generates it)
// ---------------------------------------------------------------------------
__device__ __forceinline__ void fma2(uint64_t& acc, uint64_t a, uint64_t b) {
    asm("fma.rn.f32x2 %0, %1, %2, %0;" : "+l"(acc) : "l"(a), "l"(b));
}
__device__ __forceinline__ float hsum2(uint64_t v) {
    float lo, hi;
    asm("mov.b64 {%0, %1}, %2;" : "=f"(lo), "=f"(hi) : "l"(v));
    return lo + hi;
}
__device__ __forceinline__ void lds_v2u64(uint64_t& a, uint64_t& b, unsigned saddr) {
    asm("ld.shared.v2.b64 {%0, %1}, [%2];" : "=l"(a), "=l"(b) : "r"(saddr));
}
__device__ __forceinline__ void ldg_nc_v2u64(uint64_t& a, uint64_t& b, const float* p) {
    asm("ld.global.nc.v2.b64 {%0, %1}, [%2];" : "=l"(a), "=l"(b) : "l"(p));
}

// ---------------------------------------------------------------------------
// Phase 1: x_proj[n,m,h] = sum_i x[n,m,i] * w_ih[n,h,i] + b_ih[n,h]
// (unchanged from R8 — ~0.9ms, near its FFMA2 issue floor)
// ---------------------------------------------------------------------------
__global__ __launch_bounds__(256, 2) void xproj_kernel(
    const float* __restrict__ x, const float* __restrict__ w_ih,
    const float* __restrict__ b_ih, float* __restrict__ out)
{
    __shared__ float As[128][20];   // padded rows (80B) for conflict avoidance
    __shared__ float Ws[64][20];

    const int tid = threadIdx.x;
    const int net = blockIdx.z;
    const int bm  = blockIdx.x * 128;
    const int bn  = blockIdx.y * 64;
    const int tx  = tid & 15;       // n-dim: locals {tx, tx+16, tx+32, tx+48}
    const int ty  = tid >> 4;       // m-dim: locals ty*8 .. ty*8+7

    const float* xA = x    + (size_t)net * BB * TT * II + (size_t)bm * II;
    const float* xW = w_ih + (size_t)net * HH * II      + (size_t)bn * II;

    uint64_t acc[8][4];
#pragma unroll
    for (int i = 0; i < 8; i++)
#pragma unroll
        for (int j = 0; j < 4; j++) acc[i][j] = 0ull;

    const int arow = tid >> 2, ac4 = tid & 3;
    const int wrow = tid >> 2, wc4 = tid & 3;

    for (int kt = 0; kt < II; kt += 16) {
        float4 a0 = *(const float4*)(xA + (size_t)arow        * II + kt + ac4 * 4);
        float4 a1 = *(const float4*)(xA + (size_t)(arow + 64) * II + kt + ac4 * 4);
        float4 w0 = *(const float4*)(xW + (size_t)wrow        * II + kt + wc4 * 4);
        __syncthreads();
        *(float4*)&As[arow][ac4 * 4]      = a0;
        *(float4*)&As[arow + 64][ac4 * 4] = a1;
        *(float4*)&Ws[wrow][wc4 * 4]      = w0;
        __syncthreads();
#pragma unroll
        for (int kk = 0; kk < 16; kk += 4) {
            uint64_t wv[4][2];
#pragma unroll
            for (int ni = 0; ni < 4; ni++) {
                unsigned sa = (unsigned)__cvta_generic_to_shared(&Ws[tx + ni * 16][kk]);
                lds_v2u64(wv[ni][0], wv[ni][1], sa);
            }
#pragma unroll
            for (int mi = 0; mi < 8; mi++) {
                uint64_t a01, a23;
                unsigned sa = (unsigned)__cvta_generic_to_shared(&As[ty * 8 + mi][kk]);
                lds_v2u64(a01, a23, sa);
#pragma unroll
                for (int ni = 0; ni < 4; ni++) {
                    fma2(acc[mi][ni], a01, wv[ni][0]);
                    fma2(acc[mi][ni], a23, wv[ni][1]);
                }
            }
        }
    }

    float bias[4];
#pragma unroll
    for (int ni = 0; ni < 4; ni++) bias[ni] = b_ih[net * HH + bn + tx + ni * 16];

    float* orow = out + (size_t)net * BB * TT * HH + (size_t)(bm + ty * 8) * HH + bn;
#pragma unroll
    for (int mi = 0; mi < 8; mi++)
#pragma unroll
        for (int ni = 0; ni < 4; ni++)
            orow[(size_t)mi * HH + tx + ni * 16] = hsum2(acc[mi][ni]) + bias[ni];
}

// ---------------------------------------------------------------------------
// Phase 2: persistent recurrent scan.
// 128 CTAs = 16 nets x 8 groups. CTA owns 64 channels x 16 batches.
// 8 warps = 2 o-groups x 4-way K-split; lane = 1 channel.
// KEY CHANGE (R9): each thread's w_hh slice (128 floats) lives in REGISTERS,
// loaded once before the t-loop. Inner loop = broadcast LDS + FFMA2 only —
// eliminates the 32-lines-per-LDG wavefront storm that bound R8 at L1=69%.
// ---------------------------------------------------------------------------
__global__ __launch_bounds__(256, 1) void rnn_scan_kernel(
    const float* __restrict__ w_hh, const float* __restrict__ b_hh,
    float* __restrict__ out)
{
    __shared__ float h_s[BB][HH];          // 32 KB; first 16 KB reused for reduction
    float* red = &h_s[0][0];

    const int tid   = threadIdx.x;
    const int n     = blockIdx.x >> 3;
    const int grp   = blockIdx.x & 7;
    const int wid   = tid >> 5, lane = tid & 31;
    const int ogrp  = wid & 1,  ksp  = wid >> 1;
    const int o_loc = ogrp * 32 + lane;
    const int o_glb = grp * OSL + o_loc;
    const int kbase = ksp * 128;

    const float* wrow = w_hh + ((size_t)n * HH + o_glb) * HH + kbase;
    float* hb = &g_hbuf[0][0][0][0];

    // Hoist this thread's 128 w_hh values into registers (loop-invariant).
    uint64_t wreg[64];
#pragma unroll
    for (int j = 0; j < 32; j++)
        ldg_nc_v2u64(wreg[2 * j], wreg[2 * j + 1], wrow + 4 * j);

    // Per-thread epilogue constants: thread handles flat outputs j = r*256+tid.
    float  bh[4];
    size_t xoff[4];
    int    hoff[4];
#pragma unroll
    for (int r = 0; r < 4; r++) {
        int j = (r << 8) + tid;
        int b = j >> 6, oo = j & 63;
        int og = grp * OSL + oo;
        bh[r]   = b_hh[n * HH + og];
        xoff[r] = ((size_t)(n * BB + b)) * TT * HH + og;
        hoff[r] = (n * BB + b) * HH + og;
    }
    const int SLAB = NNET * BB * HH;

    unsigned target = 0;

    for (int t = 0; t < TT; ++t) {
        const int p = t & 1;

        // Prefetch this step's x_proj values (hide L2 latency behind staging+GEMM).
        float xv[4];
#pragma unroll
        for (int r = 0; r < 4; r++) xv[r] = out[xoff[r] + (size_t)t * HH];

        // Stage h_prev into smem. __ldcg: bypass L1 (written by other CTAs).
        const float4* src = (const float4*)(hb + (size_t)p * SLAB + n * BB * HH);
        float4* dst = (float4*)&h_s[0][0];
#pragma unroll
        for (int i = 0; i < 8; i++) dst[tid + (i << 8)] = __ldcg(src + tid + (i << 8));
        __syncthreads();

        // GEMM: acc[b] += h[b][k..] * wreg[k..]. Broadcast LDS, zero LDG.
        uint64_t acc[16];
#pragma unroll
        for (int b = 0; b < 16; b++) acc[b] = 0ull;
        const unsigned hbase = (unsigned)__cvta_generic_to_shared(&h_s[0][kbase]);
#pragma unroll
        for (int kk = 0; kk < 32; kk++) {
            const uint64_t w01 = wreg[2 * kk];
            const uint64_t w23 = wreg[2 * kk + 1];
#pragma unroll
            for (int b = 0; b < 16; b++) {
                uint64_t h01, h23;
                lds_v2u64(h01, h23, hbase + b * (HH * 4) + kk * 16);
                fma2(acc[b], h01, w01);
                fma2(acc[b], h23, w23);
            }
        }
        __syncthreads();   // all warps done reading h_s -> safe to reuse as red

        // K-split partials: red[(b*64 + o_loc)*4 + ksp]
#pragma unroll
        for (int b = 0; b < 16; b++)
            red[((((b << 6) | o_loc)) << 2) + ksp] = hsum2(acc[b]);
        __syncthreads();

        // Reduce 4 partials, add bias + x_proj, tanh, store everywhere needed.
        const int pnew = p ^ 1;
#pragma unroll
        for (int r = 0; r < 4; r++) {
            int j = (r << 8) + tid;
            float4 pr = *(const float4*)&red[j << 2];
            float s  = (pr.x + pr.y) + (pr.z + pr.w) + bh[r];
            float hv = tanhf(xv[r] + s);
            out[xoff[r] + (size_t)t * HH] = hv;
            hb[(size_t)pnew * SLAB + hoff[r]] = hv;
            if (t == TT - 1) out[OUT_XP + hoff[r]] = hv;
        }

        // Cross-CTA step barrier for this network (8 CTAs).
        __threadfence();
        __syncthreads();
        target += GROUPS;
        if (tid == 0) {
            atomicAdd(&g_cnt[n], 1u);
            volatile unsigned* vc = (volatile unsigned*)&g_cnt[n];
            while (*vc < target) { }
        }
        __syncthreads();
    }
}

// ---------------------------------------------------------------------------
// Launch. Inputs (metadata order): x, w_ih, w_hh, b_ih, b_hh. Output: fp32
// concat(output[N,B,T,H], h_n[N,B,H]).
// ---------------------------------------------------------------------------
extern "C" void kernel_launch(void* const* d_in, const int* in_sizes, int n_in,
                              void* d_out, int out_size)
{
    (void)in_sizes; (void)n_in; (void)out_size;
    const float* x    = (const float*)d_in[0];
    const float* w_ih = (const float*)d_in[1];
    const float* w_hh = (const float*)d_in[2];
    const float* b_ih = (const float*)d_in[3];
    const float* b_hh = (const float*)d_in[4];
    float* out = (float*)d_out;

    void* hb = nullptr;  void* cp = nullptr;
    cudaGetSymbolAddress(&hb, g_hbuf);
    cudaGetSymbolAddress(&cp, g_cnt);
    cudaMemsetAsync(hb, 0, sizeof(float) * NNET * BB * HH, 0);
    cudaMemsetAsync(cp, 0, sizeof(unsigned) * NNET, 0);

    dim3 g1(TT * BB / 128, HH / 64, NNET);   // 64 x 8 x 16
    xproj_kernel<<<g1, 256>>>(x, w_ih, b_ih, out);

    rnn_scan_kernel<<<NNET * GROUPS, 256>>>(w_hh, b_hh, out);
}

// round 11
// speedup vs baseline: 1.4686x; 1.0245x over previous
#include <cuda_runtime.h>
#include <cstdint>
#include <cstddef>

#define NNET 16
#define BB   16
#define TT   512
#define II   256
#define HH   512
#define GROUPS 8          // CTAs per network in the scan kernel
#define OSL  64           // output channels per scan CTA
#define KSPLIT 8          // K-split ways in the scan (16 warps = 2 ogrp x 8 ksp)
#define OUT_XP (NNET * BB * TT * HH)   // element offset of h_n section in d_out

// Persistent state for the scan (double-buffered h + per-net arrival counters).
__device__ float    g_hbuf[2][NNET][BB][HH];
__device__ unsigned g_cnt[NNET][32];     // one 128B line per net (L2 atomic spread)

// ---------------------------------------------------------------------------
// f32x2 helpers (FFMA2 is PTX-only; ptxas never auto-generates it)
// ---------------------------------------------------------------------------
__device__ __forceinline__ void fma2(uint64_t& acc, uint64_t a, uint64_t b) {
    asm("fma.rn.f32x2 %0, %1, %2, %0;" : "+l"(acc) : "l"(a), "l"(b));
}
__device__ __forceinline__ float hsum2(uint64_t v) {
    float lo, hi;
    asm("mov.b64 {%0, %1}, %2;" : "=f"(lo), "=f"(hi) : "l"(v));
    return lo + hi;
}
__device__ __forceinline__ void lds_v2u64(uint64_t& a, uint64_t& b, unsigned saddr) {
    asm("ld.shared.v2.b64 {%0, %1}, [%2];" : "=l"(a), "=l"(b) : "r"(saddr));
}
__device__ __forceinline__ void ldg_nc_v2u64(uint64_t& a, uint64_t& b, const float* p) {
    asm("ld.global.nc.v2.b64 {%0, %1}, [%2];" : "=l"(a), "=l"(b) : "l"(p));
}

// ---------------------------------------------------------------------------
// Phase 1: x_proj[n,m,h] = sum_i x[n,m,i] * w_ih[n,h,i] + b_ih[n,h]
// (unchanged — ~0.89ms, ~53% of FFMA2 issue floor)
// ---------------------------------------------------------------------------
__global__ __launch_bounds__(256, 2) void xproj_kernel(
    const float* __restrict__ x, const float* __restrict__ w_ih,
    const float* __restrict__ b_ih, float* __restrict__ out)
{
    __shared__ float As[128][20];
    __shared__ float Ws[64][20];

    const int tid = threadIdx.x;
    const int net = blockIdx.z;
    const int bm  = blockIdx.x * 128;
    const int bn  = blockIdx.y * 64;
    const int tx  = tid & 15;
    const int ty  = tid >> 4;

    const float* xA = x    + (size_t)net * BB * TT * II + (size_t)bm * II;
    const float* xW = w_ih + (size_t)net * HH * II      + (size_t)bn * II;

    uint64_t acc[8][4];
#pragma unroll
    for (int i = 0; i < 8; i++)
#pragma unroll
        for (int j = 0; j < 4; j++) acc[i][j] = 0ull;

    const int arow = tid >> 2, ac4 = tid & 3;
    const int wrow = tid >> 2, wc4 = tid & 3;

    for (int kt = 0; kt < II; kt += 16) {
        float4 a0 = *(const float4*)(xA + (size_t)arow        * II + kt + ac4 * 4);
        float4 a1 = *(const float4*)(xA + (size_t)(arow + 64) * II + kt + ac4 * 4);
        float4 w0 = *(const float4*)(xW + (size_t)wrow        * II + kt + wc4 * 4);
        __syncthreads();
        *(float4*)&As[arow][ac4 * 4]      = a0;
        *(float4*)&As[arow + 64][ac4 * 4] = a1;
        *(float4*)&Ws[wrow][wc4 * 4]      = w0;
        __syncthreads();
#pragma unroll
        for (int kk = 0; kk < 16; kk += 4) {
            uint64_t wv[4][2];
#pragma unroll
            for (int ni = 0; ni < 4; ni++) {
                unsigned sa = (unsigned)__cvta_generic_to_shared(&Ws[tx + ni * 16][kk]);
                lds_v2u64(wv[ni][0], wv[ni][1], sa);
            }
#pragma unroll
            for (int mi = 0; mi < 8; mi++) {
                uint64_t a01, a23;
                unsigned sa = (unsigned)__cvta_generic_to_shared(&As[ty * 8 + mi][kk]);
                lds_v2u64(a01, a23, sa);
#pragma unroll
                for (int ni = 0; ni < 4; ni++) {
                    fma2(acc[mi][ni], a01, wv[ni][0]);
                    fma2(acc[mi][ni], a23, wv[ni][1]);
                }
            }
        }
    }

    float bias[4];
#pragma unroll
    for (int ni = 0; ni < 4; ni++) bias[ni] = b_ih[net * HH + bn + tx + ni * 16];

    float* orow = out + (size_t)net * BB * TT * HH + (size_t)(bm + ty * 8) * HH + bn;
#pragma unroll
    for (int mi = 0; mi < 8; mi++)
#pragma unroll
        for (int ni = 0; ni < 4; ni++)
            orow[(size_t)mi * HH + tx + ni * 16] = hsum2(acc[mi][ni]) + bias[ni];
}

// ---------------------------------------------------------------------------
// Phase 2: persistent recurrent scan — 16 warps (4/SMSP) for latency hiding.
// 128 CTAs = 16 nets x 8 groups. CTA owns 64 channels x 16 batches.
// 16 warps = 2 o-groups x 8-way K-split; lane = 1 channel, 64 w_hh floats in
// registers per thread. Separate reduction buffer ([ksp][out] layout,
// conflict-free STS). Early barrier arrival overlaps out[] stores with spin.
// ---------------------------------------------------------------------------
__global__ __launch_bounds__(512, 1) void rnn_scan_kernel(
    const float* __restrict__ w_hh, const float* __restrict__ b_hh,
    float* __restrict__ out)
{
    __shared__ float h_s[BB][HH];                  // 32 KB staged h_prev
    __shared__ float red[KSPLIT][BB * OSL];        // 32 KB k-split partials

    const int tid   = threadIdx.x;
    const int n     = blockIdx.x >> 3;
    const int grp   = blockIdx.x & 7;
    const int wid   = tid >> 5, lane = tid & 31;
    const int ogrp  = wid & 1,  ksp  = wid >> 1;   // ksp in 0..7
    const int o_loc = ogrp * 32 + lane;
    const int o_glb = grp * OSL + o_loc;
    const int kbase = ksp * 64;

    const float* wrow = w_hh + ((size_t)n * HH + o_glb) * HH + kbase;
    float* hb = &g_hbuf[0][0][0][0];

    // Hoist this thread's 64 w_hh values into registers (loop-invariant).
    uint64_t wreg[32];
#pragma unroll
    for (int j = 0; j < 16; j++)
        ldg_nc_v2u64(wreg[2 * j], wreg[2 * j + 1], wrow + 4 * j);

    // Per-thread epilogue constants: thread handles flat outputs j = r*512+tid.
    float    bh[2];
    unsigned xoff[2];   // element index into out[] minus t*HH (fits 32-bit)
    unsigned hoff[2];   // element index into one h-buffer slab
#pragma unroll
    for (int r = 0; r < 2; r++) {
        int j = (r << 9) + tid;
        int b = j >> 6, oo = j & 63;
        int og = grp * OSL + oo;
        bh[r]   = b_hh[n * HH + og];
        xoff[r] = (unsigned)((n * BB + b) * TT * HH + og);
        hoff[r] = (unsigned)((n * BB + b) * HH + og);
    }
    const unsigned SLAB = NNET * BB * HH;

    unsigned target = 0;

    for (int t = 0; t < TT; ++t) {
        const int p = t & 1;

        // Prefetch this step's x_proj values (hidden behind staging + GEMM).
        float xv[2];
#pragma unroll
        for (int r = 0; r < 2; r++) xv[r] = out[xoff[r] + (unsigned)t * HH];

        // Stage h_prev into smem. __ldcg: bypass L1 (written by other CTAs).
        const float4* src = (const float4*)(hb + (size_t)p * SLAB + n * BB * HH);
        float4* dst = (float4*)&h_s[0][0];
#pragma unroll
        for (int i = 0; i < 4; i++) dst[tid + (i << 9)] = __ldcg(src + tid + (i << 9));
        __syncthreads();                                     // sync 1: h staged

        // GEMM: acc[b] += h[b][kbase+..] * wreg[..]. Broadcast LDS + FFMA2 only.
        uint64_t acc[16];
#pragma unroll
        for (int b = 0; b < 16; b++) acc[b] = 0ull;
        const unsigned hbase = (unsigned)__cvta_generic_to_shared(&h_s[0][kbase]);
#pragma unroll
        for (int kk = 0; kk < 16; kk++) {
            const uint64_t w01 = wreg[2 * kk];
            const uint64_t w23 = wreg[2 * kk + 1];
#pragma unroll
            for (int b = 0; b < 16; b++) {
                uint64_t h01, h23;
                lds_v2u64(h01, h23, hbase + b * (HH * 4) + kk * 16);
                fma2(acc[b], h01, w01);
                fma2(acc[b], h23, w23);
            }
        }

        // K-split partials into separate buffer: red[ksp][b*64 + o_loc].
        // (h_s still being read by other warps is fine — red is distinct.)
#pragma unroll
        for (int b = 0; b < 16; b++)
            red[ksp][(b << 6) | o_loc] = hsum2(acc[b]);
        __syncthreads();                                     // sync 2: partials in

        // Reduce 8 partials, add bias + x_proj, tanh; publish h first.
        const int pnew = p ^ 1;
        float hv[2];
#pragma unroll
        for (int r = 0; r < 2; r++) {
            int j = (r << 9) + tid;
            float s = bh[r];
#pragma unroll
            for (int q = 0; q < 8; q++) s += red[q][j];
            hv[r] = tanhf(xv[r] + s);
            hb[pnew * SLAB + hoff[r]] = hv[r];               // what peers need
        }
        __threadfence();
        __syncthreads();                                     // sync 3: h published

        // Early arrival: tid0 signals first, then everyone (incl. tid0) does
        // the out[] stores while peer CTAs are still arriving; tid0 spins last.
        target += GROUPS;
        if (tid == 0) atomicAdd(&g_cnt[n][0], 1u);
#pragma unroll
        for (int r = 0; r < 2; r++) {
            out[xoff[r] + (unsigned)t * HH] = hv[r];
            if (t == TT - 1) out[OUT_XP + hoff[r]] = hv[r];
        }
        if (tid == 0) {
            volatile unsigned* vc = (volatile unsigned*)&g_cnt[n][0];
            while (*vc < target) { }
        }
        __syncthreads();                                     // sync 4: barrier done
    }
}

// ---------------------------------------------------------------------------
// Launch. Inputs (metadata order): x, w_ih, w_hh, b_ih, b_hh. Output: fp32
// concat(output[N,B,T,H], h_n[N,B,H]).
// ---------------------------------------------------------------------------
extern "C" void kernel_launch(void* const* d_in, const int* in_sizes, int n_in,
                              void* d_out, int out_size)
{
    (void)in_sizes; (void)n_in; (void)out_size;
    const float* x    = (const float*)d_in[0];
    const float* w_ih = (const float*)d_in[1];
    const float* w_hh = (const float*)d_in[2];
    const float* b_ih = (const float*)d_in[3];
    const float* b_hh = (const float*)d_in[4];
    float* out = (float*)d_out;

    void* hb = nullptr;  void* cp = nullptr;
    cudaGetSymbolAddress(&hb, g_hbuf);
    cudaGetSymbolAddress(&cp, g_cnt);
    cudaMemsetAsync(hb, 0, sizeof(float) * NNET * BB * HH, 0);
    cudaMemsetAsync(cp, 0, sizeof(unsigned) * NNET * 32, 0);

    dim3 g1(TT * BB / 128, HH / 64, NNET);   // 64 x 8 x 16
    xproj_kernel<<<g1, 256>>>(x, w_ih, b_ih, out);

    rnn_scan_kernel<<<NNET * GROUPS, 512>>>(w_hh, b_hh, out);
}